// round 7
// baseline (speedup 1.0000x reference)
#include <cuda_runtime.h>
#include <cstdint>

// ---------------------------------------------------------------------------
// GenAttentionMask (float32 output: 1.0f / 0.0f):
//   for b in range(batch):
//     s = seq_lengths[b]
//     out += head_num copies of (fp16(mask[b,0,:s,:s]) > 0.5) as float32
//
// fp16_rn(x) > 0.5  <=>  x > 0.500244140625f   (fp16 midpoint, ties-to-even)
//
// One thread handles 8 consecutive elements (2x float4); adjacent lanes own
// adjacent float4 pairs so every LDG.128/STG.128 is fully coalesced. Streaming
// cache hints (.cs) keep the 428MB write stream from churning L2.
// ---------------------------------------------------------------------------

#define MAX_BATCH 16
#define THRESH 0.500244140625f

struct Meta {
    int       sl[MAX_BATCH];
    long long outbase[MAX_BATCH];   // element offset of batch b's output region
    int       hn;
};

__device__ Meta g_meta;

__global__ void setup_kernel(const int* __restrict__ sl, const int* __restrict__ hn_ptr, int batch) {
    int hn = hn_ptr ? *hn_ptr : 8;
    if (hn <= 0 || hn > 64) hn = 8;   // sanity clamp
    g_meta.hn = hn;
    long long acc = 0;
    for (int b = 0; b < batch && b < MAX_BATCH; ++b) {
        int s = sl[b];
        g_meta.sl[b] = s;
        g_meta.outbase[b] = acc;
        acc += (long long)hn * (long long)s * (long long)s;
    }
}

__device__ __forceinline__ float4 thresh4(float4 f) {
    float4 v;
    v.x = (f.x > THRESH) ? 1.0f : 0.0f;
    v.y = (f.y > THRESH) ? 1.0f : 0.0f;
    v.z = (f.z > THRESH) ? 1.0f : 0.0f;
    v.w = (f.w > THRESH) ? 1.0f : 0.0f;
    return v;
}

// One thread: 8 consecutive elements of one row, written to all head replicas.
__global__ void __launch_bounds__(256)
genmask_kernel(const float* __restrict__ in, float* __restrict__ out,
               int max_seq, int shift) {
    const int b = blockIdx.y;
    const int s = g_meta.sl[b];

    const int gid = blockIdx.x * blockDim.x + threadIdx.x;
    const int row = gid >> shift;
    const int col = (gid & ((1 << shift) - 1)) << 3;   // 8 elements per thread
    if (row >= s || col >= s) return;

    const float4* ip = reinterpret_cast<const float4*>(
        in + (size_t)b * max_seq * max_seq + (size_t)row * max_seq + col);
    float4 f0 = __ldcs(ip);
    float4 f1 = __ldcs(ip + 1);

    float4 v0 = thresh4(f0);
    float4 v1 = thresh4(f1);

    const size_t ss = (size_t)s * (size_t)s;  // head stride (elements)
    float* op = out + (size_t)g_meta.outbase[b] + (size_t)row * s + col;
    const int hn = g_meta.hn;

#pragma unroll 8
    for (int h = 0; h < hn; ++h) {
        __stcs(reinterpret_cast<float4*>(op),     v0);
        __stcs(reinterpret_cast<float4*>(op) + 1, v1);
        op += ss;
    }
}

extern "C" void kernel_launch(void* const* d_in, const int* in_sizes, int n_in,
                              void* d_out, int out_size) {
    // Identify inputs by size, not position:
    //   mask        = largest input
    //   head_num    = 1-element input
    //   seq_lengths = the remaining one (batch = its element count)
    int mask_i = 0;
    for (int i = 1; i < n_in; ++i)
        if (in_sizes[i] > in_sizes[mask_i]) mask_i = i;
    int hn_i = -1, sl_i = -1;
    for (int i = 0; i < n_in; ++i) {
        if (i == mask_i) continue;
        if (in_sizes[i] == 1 && hn_i < 0) hn_i = i;
        else sl_i = i;
    }

    const float* mask = (const float*)d_in[mask_i];
    const int*   sl   = (const int*)d_in[sl_i];
    const int*   hn   = (hn_i >= 0) ? (const int*)d_in[hn_i] : nullptr;
    float* out = (float*)d_out;

    const int batch = in_sizes[sl_i];
    const long long msq = (long long)in_sizes[mask_i] / batch;   // max_seq^2

    // max_seq is a power of two (2048 here); recover it robustly
    int max_seq = 1;
    while ((long long)max_seq * max_seq < msq) max_seq <<= 1;

    const int gpr_pad = max_seq / 8;      // padded 8-elem groups per row (pow2)
    int shift = 0;
    while ((1 << shift) < gpr_pad) ++shift;

    setup_kernel<<<1, 1>>>(sl, hn, batch);

    const long long threads_per_batch = (long long)max_seq * gpr_pad;
    dim3 block(256);
    dim3 grid((unsigned)((threads_per_batch + 255) / 256), batch);
    genmask_kernel<<<grid, block>>>(mask, out, max_seq, shift);
}

// round 8
// speedup vs baseline: 1.3337x; 1.3337x over previous
#include <cuda_runtime.h>
#include <cstdint>

// ---------------------------------------------------------------------------
// GenAttentionMask (float32 output: 1.0f / 0.0f):
//   for b in range(batch):
//     s = seq_lengths[b]
//     out += head_num copies of (fp16(mask[b,0,:s,:s]) > 0.5) as float32
//
// fp16_rn(x) > 0.5  <=>  x > 0.500244140625f   (fp16 midpoint, ties-to-even)
//
// Coalescing: adjacent lanes own ADJACENT float4s. Each thread handles two
// float4s half a row apart (both warp-contiguous), giving MLP=2 on loads and
// fully-covered 128B lines on every store. Output stores use .cs (evict-first)
// since the 428MB stream is never re-read.
// ---------------------------------------------------------------------------

#define MAX_BATCH 16
#define THRESH 0.500244140625f

struct Meta {
    int       sl[MAX_BATCH];
    long long outbase[MAX_BATCH];   // element offset of batch b's output region
    int       hn;
};

__device__ Meta g_meta;

__global__ void setup_kernel(const int* __restrict__ sl, const int* __restrict__ hn_ptr, int batch) {
    int hn = hn_ptr ? *hn_ptr : 8;
    if (hn <= 0 || hn > 64) hn = 8;   // sanity clamp
    g_meta.hn = hn;
    long long acc = 0;
    for (int b = 0; b < batch && b < MAX_BATCH; ++b) {
        int s = sl[b];
        g_meta.sl[b] = s;
        g_meta.outbase[b] = acc;
        acc += (long long)hn * (long long)s * (long long)s;
    }
}

__device__ __forceinline__ float4 thresh4(float4 f) {
    float4 v;
    v.x = (f.x > THRESH) ? 1.0f : 0.0f;
    v.y = (f.y > THRESH) ? 1.0f : 0.0f;
    v.z = (f.z > THRESH) ? 1.0f : 0.0f;
    v.w = (f.w > THRESH) ? 1.0f : 0.0f;
    return v;
}

// One thread: two float4s of one row (cols col and col + s/2), written to all
// head replicas. shift indexes float4-groups per HALF row.
__global__ void __launch_bounds__(256)
genmask_kernel(const float* __restrict__ in, float* __restrict__ out,
               int max_seq, int shift) {
    const int b = blockIdx.y;
    const int s = g_meta.sl[b];

    const int gid = blockIdx.x * blockDim.x + threadIdx.x;
    const int row  = gid >> shift;
    const int col  = (gid & ((1 << shift) - 1)) << 2;   // within first half-row
    const int half = s >> 1;
    if (row >= s || col >= half) return;

    const float* ib = in + (size_t)b * max_seq * max_seq + (size_t)row * max_seq;
    float4 f0 = *reinterpret_cast<const float4*>(ib + col);
    float4 f1 = *reinterpret_cast<const float4*>(ib + half + col);

    float4 v0 = thresh4(f0);
    float4 v1 = thresh4(f1);

    const size_t ss = (size_t)s * (size_t)s;  // head stride (elements)
    float* op = out + (size_t)g_meta.outbase[b] + (size_t)row * s + col;
    const int hn = g_meta.hn;

#pragma unroll 8
    for (int h = 0; h < hn; ++h) {
        __stcs(reinterpret_cast<float4*>(op), v0);
        __stcs(reinterpret_cast<float4*>(op + half), v1);
        op += ss;
    }
}

extern "C" void kernel_launch(void* const* d_in, const int* in_sizes, int n_in,
                              void* d_out, int out_size) {
    // Identify inputs by size, not position:
    //   mask        = largest input
    //   head_num    = 1-element input
    //   seq_lengths = the remaining one (batch = its element count)
    int mask_i = 0;
    for (int i = 1; i < n_in; ++i)
        if (in_sizes[i] > in_sizes[mask_i]) mask_i = i;
    int hn_i = -1, sl_i = -1;
    for (int i = 0; i < n_in; ++i) {
        if (i == mask_i) continue;
        if (in_sizes[i] == 1 && hn_i < 0) hn_i = i;
        else sl_i = i;
    }

    const float* mask = (const float*)d_in[mask_i];
    const int*   sl   = (const int*)d_in[sl_i];
    const int*   hn   = (hn_i >= 0) ? (const int*)d_in[hn_i] : nullptr;
    float* out = (float*)d_out;

    const int batch = in_sizes[sl_i];
    const long long msq = (long long)in_sizes[mask_i] / batch;   // max_seq^2

    // max_seq is a power of two (2048 here); recover it robustly
    int max_seq = 1;
    while ((long long)max_seq * max_seq < msq) max_seq <<= 1;

    // float4-groups per HALF row, padded to a power of two
    const int gpr_pad = max_seq / 8;
    int shift = 0;
    while ((1 << shift) < gpr_pad) ++shift;

    setup_kernel<<<1, 1>>>(sl, hn, batch);

    const long long threads_per_batch = (long long)max_seq * gpr_pad;
    dim3 block(256);
    dim3 grid((unsigned)((threads_per_batch + 255) / 256), batch);
    genmask_kernel<<<grid, block>>>(mask, out, max_seq, shift);
}

// round 9
// speedup vs baseline: 1.3365x; 1.0020x over previous
#include <cuda_runtime.h>
#include <cstdint>

// ---------------------------------------------------------------------------
// GenAttentionMask (float32 output: 1.0f / 0.0f):
//   for b in range(batch):
//     s = seq_lengths[b]
//     out += head_num copies of (fp16(mask[b,0,:s,:s]) > 0.5) as float32
//
// fp16_rn(x) > 0.5  <=>  x > 0.500244140625f   (fp16 midpoint, ties-to-even)
//
// Coalescing + MLP: adjacent lanes own adjacent float4s. Each thread handles
// FOUR float4s at quarter-row offsets (all warp-contiguous), front-batched
// loads for MLP=4, then 32 independent fully-covered STG.128 (.cs, write-once
// stream).
// ---------------------------------------------------------------------------

#define MAX_BATCH 16
#define THRESH 0.500244140625f

struct Meta {
    int       sl[MAX_BATCH];
    long long outbase[MAX_BATCH];   // element offset of batch b's output region
    int       hn;
};

__device__ Meta g_meta;

__global__ void setup_kernel(const int* __restrict__ sl, const int* __restrict__ hn_ptr, int batch) {
    int hn = hn_ptr ? *hn_ptr : 8;
    if (hn <= 0 || hn > 64) hn = 8;   // sanity clamp
    g_meta.hn = hn;
    long long acc = 0;
    for (int b = 0; b < batch && b < MAX_BATCH; ++b) {
        int s = sl[b];
        g_meta.sl[b] = s;
        g_meta.outbase[b] = acc;
        acc += (long long)hn * (long long)s * (long long)s;
    }
}

__device__ __forceinline__ float4 thresh4(float4 f) {
    float4 v;
    v.x = (f.x > THRESH) ? 1.0f : 0.0f;
    v.y = (f.y > THRESH) ? 1.0f : 0.0f;
    v.z = (f.z > THRESH) ? 1.0f : 0.0f;
    v.w = (f.w > THRESH) ? 1.0f : 0.0f;
    return v;
}

// One thread: four float4s of one row (quarter-row apart), written to all
// head replicas. shift indexes float4-groups per QUARTER row.
__global__ void __launch_bounds__(256)
genmask_kernel(const float* __restrict__ in, float* __restrict__ out,
               int max_seq, int shift) {
    const int b = blockIdx.y;
    const int s = g_meta.sl[b];

    const int gid = blockIdx.x * blockDim.x + threadIdx.x;
    const int row = gid >> shift;
    const int col = (gid & ((1 << shift) - 1)) << 2;   // within first quarter
    const int q   = s >> 2;
    if (row >= s || col >= q) return;

    const float* ib = in + (size_t)b * max_seq * max_seq + (size_t)row * max_seq + col;
    // front-batched loads: MLP = 4
    float4 f0 = *reinterpret_cast<const float4*>(ib);
    float4 f1 = *reinterpret_cast<const float4*>(ib + q);
    float4 f2 = *reinterpret_cast<const float4*>(ib + 2 * q);
    float4 f3 = *reinterpret_cast<const float4*>(ib + 3 * q);

    float4 v0 = thresh4(f0);
    float4 v1 = thresh4(f1);
    float4 v2 = thresh4(f2);
    float4 v3 = thresh4(f3);

    const size_t ss = (size_t)s * (size_t)s;  // head stride (elements)
    float* op = out + (size_t)g_meta.outbase[b] + (size_t)row * s + col;
    const int hn = g_meta.hn;

#pragma unroll 8
    for (int h = 0; h < hn; ++h) {
        __stcs(reinterpret_cast<float4*>(op),         v0);
        __stcs(reinterpret_cast<float4*>(op + q),     v1);
        __stcs(reinterpret_cast<float4*>(op + 2 * q), v2);
        __stcs(reinterpret_cast<float4*>(op + 3 * q), v3);
        op += ss;
    }
}

extern "C" void kernel_launch(void* const* d_in, const int* in_sizes, int n_in,
                              void* d_out, int out_size) {
    // Identify inputs by size, not position:
    //   mask        = largest input
    //   head_num    = 1-element input
    //   seq_lengths = the remaining one (batch = its element count)
    int mask_i = 0;
    for (int i = 1; i < n_in; ++i)
        if (in_sizes[i] > in_sizes[mask_i]) mask_i = i;
    int hn_i = -1, sl_i = -1;
    for (int i = 0; i < n_in; ++i) {
        if (i == mask_i) continue;
        if (in_sizes[i] == 1 && hn_i < 0) hn_i = i;
        else sl_i = i;
    }

    const float* mask = (const float*)d_in[mask_i];
    const int*   sl   = (const int*)d_in[sl_i];
    const int*   hn   = (hn_i >= 0) ? (const int*)d_in[hn_i] : nullptr;
    float* out = (float*)d_out;

    const int batch = in_sizes[sl_i];
    const long long msq = (long long)in_sizes[mask_i] / batch;   // max_seq^2

    // max_seq is a power of two (2048 here); recover it robustly
    int max_seq = 1;
    while ((long long)max_seq * max_seq < msq) max_seq <<= 1;

    // float4-groups per QUARTER row, padded to a power of two
    const int gpr_pad = max_seq / 16;
    int shift = 0;
    while ((1 << shift) < gpr_pad) ++shift;

    setup_kernel<<<1, 1>>>(sl, hn, batch);

    const long long threads_per_batch = (long long)max_seq * gpr_pad;
    dim3 block(256);
    dim3 grid((unsigned)((threads_per_batch + 255) / 256), batch);
    genmask_kernel<<<grid, block>>>(mask, out, max_seq, shift);
}